// round 6
// baseline (speedup 1.0000x reference)
#include <cuda_runtime.h>
#include <cstdint>

#define Bn   128
#define Tn   50
#define MI   32
#define En   128
#define Dn   144
#define G3   432
#define KD   144
#define KP   148          // padded smem row stride (floats)
#define CREG 112          // k-columns of w_hh kept in registers (56 ull pairs)
#define KSP  16           // remaining k-pairs of w_hh in smem (32 floats)

typedef unsigned long long ull;

// scratch (static device globals; no runtime allocation)
__device__ float g_seq [Bn*Tn*Dn];   // embedded sequence  (6400,144)
__device__ float g_gi  [Bn*Tn*G3];   // input gates        (6400,432)
__device__ float g_hseq[Bn*Tn*Dn];   // all hidden states  (6400,144)

// ---- f32x2 helpers ---------------------------------------------------------
__device__ __forceinline__ void fma2(ull& d, ull a, ull b) {
    asm("fma.rn.f32x2 %0, %1, %2, %0;" : "+l"(d) : "l"(a), "l"(b));
}
__device__ __forceinline__ float hsum2(ull v) {
    float lo, hi;
    asm("mov.b64 {%0,%1}, %2;" : "=f"(lo), "=f"(hi) : "l"(v));
    return lo + hi;
}
__device__ __forceinline__ ull pack2(float lo, float hi) {
    ull v;
    asm("mov.b64 %0, {%1,%2};" : "=l"(v) : "f"(lo), "f"(hi));
    return v;
}

// ---------------------------------------------------------------------------
// 1) basket embedding: mean-pool item embeddings + wchange flag vector
// ---------------------------------------------------------------------------
__global__ void embed_kernel(const int* __restrict__ x,
                             const float* __restrict__ encode_w,
                             const float* __restrict__ wchange_w) {
    int bt = blockIdx.x;
    const int* xr = x + (size_t)bt * (MI + 1);
    __shared__ int s_items[MI];
    __shared__ int s_flag;
    int tid = threadIdx.x;
    if (tid < MI) s_items[tid] = xr[tid];
    if (tid == MI) s_flag = xr[MI];
    __syncthreads();

    if (tid < En) {
        float acc = 0.f;
        int cnt = 0;
        #pragma unroll
        for (int i = 0; i < MI; i++) {
            int it = s_items[i];           // warp-uniform
            if (it != 0) {
                cnt++;
                acc += encode_w[(size_t)it * En + tid];
            }
        }
        float inv = 1.f / (float)(cnt > 0 ? cnt : 1);
        g_seq[(size_t)bt * Dn + tid] = acc * inv;
    } else if (tid < Dn) {
        g_seq[(size_t)bt * Dn + tid] = wchange_w[s_flag * 16 + (tid - En)];
    }
}

// ---------------------------------------------------------------------------
// 2) C[M,N] = A[M,144] * Bm[N,144]^T + bias   (32x64 tile, 256 thr, f32x2)
//    smaller tiles -> 400-1400 CTAs -> real occupancy on 148 SMs
// ---------------------------------------------------------------------------
__global__ void __launch_bounds__(256)
gemm_tn(const float* __restrict__ A, const float* __restrict__ Bm,
        const float* __restrict__ bias, float* __restrict__ C, int N) {
    extern __shared__ float sm[];
    float* Ast = sm;              // [32][KP]
    float* Bst = sm + 32 * KP;    // [64][KP]

    int tid = threadIdx.x;
    int m0 = blockIdx.y * 32, n0 = blockIdx.x * 64;

    // prologue: A 32 rows x 36 float4 = 1152, B 64 rows x 36 float4 = 2304
    #pragma unroll
    for (int p = 0; p < 5; p++) {
        int idx = tid + p * 256;
        if (idx < 1152) {
            int r = idx / 36, c = idx - 36 * r;
            *(float4*)(Ast + r * KP + 4 * c) =
                *(const float4*)(A + (size_t)(m0 + r) * KD + 4 * c);
        }
    }
    #pragma unroll
    for (int p = 0; p < 9; p++) {
        int idx = tid + p * 256;
        int r = idx / 36, c = idx - 36 * r;
        float4 v = make_float4(0.f, 0.f, 0.f, 0.f);
        if (n0 + r < N) v = *(const float4*)(Bm + (size_t)(n0 + r) * KD + 4 * c);
        *(float4*)(Bst + r * KP + 4 * c) = v;
    }
    __syncthreads();

    int tx = tid & 15, ty = tid >> 4;           // n-lane, m-lane (16x16)
    const ulonglong2* aP[2];
    const ulonglong2* bP[4];
    #pragma unroll
    for (int i = 0; i < 2; i++)
        aP[i] = (const ulonglong2*)(Ast + (2 * ty + i) * KP);
    #pragma unroll
    for (int j = 0; j < 4; j++)
        bP[j] = (const ulonglong2*)(Bst + (tx + 16 * j) * KP);

    ull acc[2][4];
    #pragma unroll
    for (int i = 0; i < 2; i++)
        #pragma unroll
        for (int j = 0; j < 4; j++) acc[i][j] = 0ull;

    #pragma unroll 6
    for (int kq = 0; kq < 36; kq++) {            // 4 k per iteration
        ulonglong2 a[2], b[4];
        #pragma unroll
        for (int i = 0; i < 2; i++) a[i] = aP[i][kq];
        #pragma unroll
        for (int j = 0; j < 4; j++) b[j] = bP[j][kq];
        #pragma unroll
        for (int i = 0; i < 2; i++)
            #pragma unroll
            for (int j = 0; j < 4; j++) {
                fma2(acc[i][j], a[i].x, b[j].x);
                fma2(acc[i][j], a[i].y, b[j].y);
            }
    }

    #pragma unroll
    for (int j = 0; j < 4; j++) {
        int n = n0 + tx + 16 * j;
        if (n < N) {
            float bv = bias[n];
            #pragma unroll
            for (int i = 0; i < 2; i++) {
                int m = m0 + 2 * ty + i;
                C[(size_t)m * N + n] = hsum2(acc[i][j]) + bv;
            }
        }
    }
}

// ---------------------------------------------------------------------------
// 3) GRU recurrence: one CTA per batch element, 432 threads = one gate row.
//    w_hh row j: k<112 in registers as f32x2 pairs, k>=112 in smem pairs.
// ---------------------------------------------------------------------------
__global__ void __launch_bounds__(G3, 1)
gru_kernel(const float* __restrict__ w_hh, const float* __restrict__ b_hh,
           const float* __restrict__ hidden, float* __restrict__ out) {
    extern __shared__ float sm[];
    ull*   s_wtp = (ull*)sm;                 // [KSP][432]  weight pairs
    float* s_h   = sm + KSP * G3 * 2;        // [144] (16B aligned)
    float* s_A   = s_h + Dn;                 // [432] gate pre-activations
    float* s_gin = s_A + G3;                 // [144] i_n stash

    int b = blockIdx.x;
    int j = threadIdx.x;

    const ull* wrow = (const ull*)(w_hh + (size_t)j * KD);   // 72 k-pairs
    ull w2[CREG / 2];
    #pragma unroll
    for (int p = 0; p < CREG / 2; p++) w2[p] = wrow[p];
    #pragma unroll
    for (int p = 0; p < KSP; p++) s_wtp[p * G3 + j] = wrow[CREG / 2 + p];

    if (j < Dn) s_h[j] = hidden[(size_t)b * Dn + j];
    float bias = b_hh[j];
    __syncthreads();

    const float* giB = g_gi + (size_t)b * Tn * G3;
    float* hsB       = g_hseq + (size_t)b * Tn * Dn;
    const ulonglong2* h2 = (const ulonglong2*)s_h;   // 16B-aligned

    float gi_cur = giB[j];                    // prefetch t=0

    for (int t = 0; t < Tn; t++) {
        ull acc0 = pack2(bias, 0.f);          // two independent chains
        ull acc1 = 0ull;
        #pragma unroll
        for (int q = 0; q < CREG / 4; q++) {           // k 0..111 (regs)
            ulonglong2 h = h2[q];
            fma2(acc0, w2[2 * q], h.x);
            fma2(acc1, w2[2 * q + 1], h.y);
        }
        #pragma unroll
        for (int q = 0; q < KSP / 2; q++) {            // k 112..143 (smem)
            ulonglong2 h = h2[CREG / 4 + q];
            fma2(acc0, s_wtp[(2 * q) * G3 + j], h.x);
            fma2(acc1, s_wtp[(2 * q + 1) * G3 + j], h.y);
        }
        float accf = hsum2(acc0) + hsum2(acc1);
        float gi_j = gi_cur;
        if (t + 1 < Tn) gi_cur = giB[(t + 1) * G3 + j];   // prefetch next

        if (j < 2 * Dn) {
            s_A[j] = gi_j + accf;                      // r, z pre-activations
        } else {
            s_A[j] = accf;                             // h_n partial
            s_gin[j - 2 * Dn] = gi_j;                  // i_n
        }
        __syncthreads();

        if (j < Dn) {
            float r = 1.f / (1.f + __expf(-s_A[j]));
            float z = 1.f / (1.f + __expf(-s_A[j + Dn]));
            float e = __expf(-2.f * (s_gin[j] + r * s_A[j + 2 * Dn]));
            float n = 2.f / (1.f + e) - 1.f;           // tanh
            float hn = (1.f - z) * n + z * s_h[j];
            s_h[j] = hn;
            hsB[t * Dn + j] = hn;
        }
        __syncthreads();
    }

    if (j < Dn) out[(size_t)Bn * Tn * En + (size_t)b * Dn + j] = s_h[j];
}

// ---------------------------------------------------------------------------
extern "C" void kernel_launch(void* const* d_in, const int* in_sizes, int n_in,
                              void* d_out, int out_size) {
    const int*   x        = (const int*)  d_in[0];
    const float* hidden   = (const float*)d_in[2];
    const float* encode_w = (const float*)d_in[3];
    const float* wchange  = (const float*)d_in[4];
    const float* w_ih     = (const float*)d_in[5];
    const float* w_hh     = (const float*)d_in[6];
    const float* b_ih     = (const float*)d_in[7];
    const float* b_hh     = (const float*)d_in[8];
    const float* fc_w     = (const float*)d_in[9];
    const float* fc_b     = (const float*)d_in[10];
    float* out = (float*)d_out;

    float *p_seq, *p_gi, *p_hseq;
    cudaGetSymbolAddress((void**)&p_seq,  g_seq);
    cudaGetSymbolAddress((void**)&p_gi,   g_gi);
    cudaGetSymbolAddress((void**)&p_hseq, g_hseq);

    const int gemm_smem = (32 + 64) * KP * 4;                     // 56832 B
    const int gru_smem  = (KSP * G3 * 2 + Dn + G3 + Dn) * 4;      // 58176 B
    cudaFuncSetAttribute(gemm_tn,    cudaFuncAttributeMaxDynamicSharedMemorySize, gemm_smem);
    cudaFuncSetAttribute(gru_kernel, cudaFuncAttributeMaxDynamicSharedMemorySize, gru_smem);

    // 1) embed
    embed_kernel<<<Bn * Tn, 160>>>(x, encode_w, wchange);

    // 2) gi = seq @ w_ih^T + b_ih   (6400 x 432)
    {
        dim3 grid((G3 + 63) / 64, (Bn * Tn) / 32);
        gemm_tn<<<grid, 256, gemm_smem>>>(p_seq, w_ih, b_ih, p_gi, G3);
    }

    // 3) GRU recurrence (one CTA per batch row), writes h_last to out tail
    gru_kernel<<<Bn, G3, gru_smem>>>(w_hh, b_hh, hidden, out);

    // 4) dynamic_user = hseq @ fc_w^T + fc_b  (6400 x 128) -> out head
    {
        dim3 grid(En / 64, (Bn * Tn) / 32);
        gemm_tn<<<grid, 256, gemm_smem>>>(p_hseq, fc_w, fc_b, out, En);
    }
}

// round 7
// speedup vs baseline: 1.1792x; 1.1792x over previous
#include <cuda_runtime.h>
#include <cstdint>

#define Bn   128
#define Tn   50
#define MI   32
#define En   128
#define Dn   144
#define G3   432
#define KD   144
#define KH   72           // GEMM k-slab
#define KP2  76           // padded slab stride (floats)
#define CREG 112          // k-columns of w_hh in registers (56 ull pairs)
#define KSP  16           // remaining k-pairs of w_hh in smem

typedef unsigned long long ull;

__device__ float g_seq [Bn*Tn*Dn];
__device__ float g_gi  [Bn*Tn*G3];
__device__ float g_hseq[Bn*Tn*Dn];

// ---- f32x2 helpers ---------------------------------------------------------
__device__ __forceinline__ void fma2(ull& d, ull a, ull b) {
    asm("fma.rn.f32x2 %0, %1, %2, %0;" : "+l"(d) : "l"(a), "l"(b));
}
__device__ __forceinline__ float hsum2(ull v) {
    float lo, hi;
    asm("mov.b64 {%0,%1}, %2;" : "=f"(lo), "=f"(hi) : "l"(v));
    return lo + hi;
}
__device__ __forceinline__ ull pack2(float lo, float hi) {
    ull v;
    asm("mov.b64 %0, {%1,%2};" : "=l"(v) : "f"(lo), "f"(hi));
    return v;
}

// ---------------------------------------------------------------------------
// 1) basket embedding (vectorized: 1 warp does the 128-wide mean pool)
// ---------------------------------------------------------------------------
__global__ void __launch_bounds__(64)
embed_kernel(const int* __restrict__ x,
             const float* __restrict__ encode_w,
             const float* __restrict__ wchange_w) {
    int bt = blockIdx.x;
    const int* xr = x + (size_t)bt * (MI + 1);
    __shared__ int s_items[MI];
    __shared__ int s_flag;
    int tid = threadIdx.x;
    if (tid < MI) s_items[tid] = xr[tid];
    if (tid == MI) s_flag = xr[MI];
    __syncthreads();

    if (tid < 32) {
        float4 acc = make_float4(0.f, 0.f, 0.f, 0.f);
        int cnt = 0;
        #pragma unroll
        for (int i = 0; i < MI; i++) {
            int it = s_items[i];                // warp-uniform
            if (it != 0) {
                cnt++;
                float4 v = *(const float4*)(encode_w + (size_t)it * En + 4 * tid);
                acc.x += v.x; acc.y += v.y; acc.z += v.z; acc.w += v.w;
            }
        }
        float inv = 1.f / (float)(cnt > 0 ? cnt : 1);
        acc.x *= inv; acc.y *= inv; acc.z *= inv; acc.w *= inv;
        *(float4*)(g_seq + (size_t)bt * Dn + 4 * tid) = acc;
    } else if (tid < 48) {
        g_seq[(size_t)bt * Dn + En + (tid - 32)] = wchange_w[s_flag * 16 + (tid - 32)];
    }
}

// ---------------------------------------------------------------------------
// 2) C[M,N] = A[M,144]*Bm[N,144]^T + bias
//    64x64 tile, 128 threads, 8x4 micro-tile, two 72-k slabs (38.9KB smem)
// ---------------------------------------------------------------------------
__global__ void __launch_bounds__(128)
gemm_tn(const float* __restrict__ A, const float* __restrict__ Bm,
        const float* __restrict__ bias, float* __restrict__ C, int N) {
    extern __shared__ float sm[];
    float* Ast = sm;              // [64][KP2]
    float* Bst = sm + 64 * KP2;   // [64][KP2]

    int tid = threadIdx.x;
    int m0 = blockIdx.y * 64, n0 = blockIdx.x * 64;
    int tx = tid & 15, ty = tid >> 4;           // n-lane(16), m-group(8)

    ull acc[8][4];
    #pragma unroll
    for (int i = 0; i < 8; i++)
        #pragma unroll
        for (int j = 0; j < 4; j++) acc[i][j] = 0ull;

    for (int ks = 0; ks < 2; ks++) {
        int k0 = ks * KH;
        // stage slab: 64 rows x 18 float4 = 1152 per matrix, 128 thr -> 9 each
        #pragma unroll
        for (int p = 0; p < 9; p++) {
            int idx = tid + p * 128;
            int r = idx / 18, c = idx - 18 * r;
            *(float4*)(Ast + r * KP2 + 4 * c) =
                *(const float4*)(A + (size_t)(m0 + r) * KD + k0 + 4 * c);
        }
        #pragma unroll
        for (int p = 0; p < 9; p++) {
            int idx = tid + p * 128;
            int r = idx / 18, c = idx - 18 * r;
            float4 v = make_float4(0.f, 0.f, 0.f, 0.f);
            if (n0 + r < N)
                v = *(const float4*)(Bm + (size_t)(n0 + r) * KD + k0 + 4 * c);
            *(float4*)(Bst + r * KP2 + 4 * c) = v;
        }
        __syncthreads();

        const float* aBase = Ast + (8 * ty) * KP2;
        const ulonglong2* bP[4];
        #pragma unroll
        for (int j = 0; j < 4; j++)
            bP[j] = (const ulonglong2*)(Bst + (tx + 16 * j) * KP2);

        #pragma unroll 6
        for (int kq = 0; kq < 18; kq++) {            // 4 k per iteration
            ulonglong2 b[4];
            #pragma unroll
            for (int j = 0; j < 4; j++) b[j] = bP[j][kq];
            #pragma unroll
            for (int i = 0; i < 8; i++) {
                ulonglong2 a = ((const ulonglong2*)(aBase + i * KP2))[kq];
                #pragma unroll
                for (int j = 0; j < 4; j++) {
                    fma2(acc[i][j], a.x, b[j].x);
                    fma2(acc[i][j], a.y, b[j].y);
                }
            }
        }
        __syncthreads();
    }

    #pragma unroll
    for (int j = 0; j < 4; j++) {
        int n = n0 + tx + 16 * j;
        if (n < N) {
            float bv = bias[n];
            #pragma unroll
            for (int i = 0; i < 8; i++) {
                int m = m0 + 8 * ty + i;
                C[(size_t)m * N + n] = hsum2(acc[i][j]) + bv;
            }
        }
    }
}

// ---------------------------------------------------------------------------
// 3) GRU recurrence: one CTA per batch element, 432 threads = one gate row.
//    w_hh row j: k<112 in registers as f32x2 pairs, k>=112 in smem pairs.
// ---------------------------------------------------------------------------
__global__ void __launch_bounds__(G3, 1)
gru_kernel(const float* __restrict__ w_hh, const float* __restrict__ b_hh,
           const float* __restrict__ hidden, float* __restrict__ out) {
    extern __shared__ float sm[];
    ull*   s_wtp = (ull*)sm;                 // [KSP][432]
    float* s_h   = sm + KSP * G3 * 2;        // [144]
    float* s_A   = s_h + Dn;                 // [432]
    float* s_gin = s_A + G3;                 // [144]

    int b = blockIdx.x;
    int j = threadIdx.x;

    const ull* wrow = (const ull*)(w_hh + (size_t)j * KD);
    ull w2[CREG / 2];
    #pragma unroll
    for (int p = 0; p < CREG / 2; p++) w2[p] = wrow[p];
    #pragma unroll
    for (int p = 0; p < KSP; p++) s_wtp[p * G3 + j] = wrow[CREG / 2 + p];

    if (j < Dn) s_h[j] = hidden[(size_t)b * Dn + j];
    float bias = b_hh[j];
    __syncthreads();

    const float* giB = g_gi + (size_t)b * Tn * G3;
    float* hsB       = g_hseq + (size_t)b * Tn * Dn;
    const ulonglong2* h2 = (const ulonglong2*)s_h;

    float gi_cur = giB[j];                    // prefetch t=0

    for (int t = 0; t < Tn; t++) {
        ull acc0 = pack2(bias, 0.f);
        ull acc1 = 0ull;
        #pragma unroll
        for (int q = 0; q < CREG / 4; q++) {           // k 0..111 (regs)
            ulonglong2 h = h2[q];
            fma2(acc0, w2[2 * q], h.x);
            fma2(acc1, w2[2 * q + 1], h.y);
        }
        #pragma unroll
        for (int q = 0; q < KSP / 2; q++) {            // k 112..143 (smem)
            ulonglong2 h = h2[CREG / 4 + q];
            fma2(acc0, s_wtp[(2 * q) * G3 + j], h.x);
            fma2(acc1, s_wtp[(2 * q + 1) * G3 + j], h.y);
        }
        float accf = hsum2(acc0) + hsum2(acc1);
        float gi_j = gi_cur;
        if (t + 1 < Tn) gi_cur = giB[(t + 1) * G3 + j];

        if (j < 2 * Dn) {
            s_A[j] = gi_j + accf;
        } else {
            s_A[j] = accf;
            s_gin[j - 2 * Dn] = gi_j;
        }
        __syncthreads();

        if (j < Dn) {
            float r = 1.f / (1.f + __expf(-s_A[j]));
            float z = 1.f / (1.f + __expf(-s_A[j + Dn]));
            float e = __expf(-2.f * (s_gin[j] + r * s_A[j + 2 * Dn]));
            float n = 2.f / (1.f + e) - 1.f;           // tanh
            float hn = (1.f - z) * n + z * s_h[j];
            s_h[j] = hn;
            hsB[t * Dn + j] = hn;
        }
        __syncthreads();
    }

    if (j < Dn) out[(size_t)Bn * Tn * En + (size_t)b * Dn + j] = s_h[j];
}

// ---------------------------------------------------------------------------
extern "C" void kernel_launch(void* const* d_in, const int* in_sizes, int n_in,
                              void* d_out, int out_size) {
    const int*   x        = (const int*)  d_in[0];
    const float* hidden   = (const float*)d_in[2];
    const float* encode_w = (const float*)d_in[3];
    const float* wchange  = (const float*)d_in[4];
    const float* w_ih     = (const float*)d_in[5];
    const float* w_hh     = (const float*)d_in[6];
    const float* b_ih     = (const float*)d_in[7];
    const float* b_hh     = (const float*)d_in[8];
    const float* fc_w     = (const float*)d_in[9];
    const float* fc_b     = (const float*)d_in[10];
    float* out = (float*)d_out;

    float *p_seq, *p_gi, *p_hseq;
    cudaGetSymbolAddress((void**)&p_seq,  g_seq);
    cudaGetSymbolAddress((void**)&p_gi,   g_gi);
    cudaGetSymbolAddress((void**)&p_hseq, g_hseq);

    const int gemm_smem = 2 * 64 * KP2 * 4;                       // 38912 B
    const int gru_smem  = (KSP * G3 * 2 + Dn + G3 + Dn) * 4;      // 58176 B
    cudaFuncSetAttribute(gru_kernel, cudaFuncAttributeMaxDynamicSharedMemorySize, gru_smem);

    // 1) embed
    embed_kernel<<<Bn * Tn, 64>>>(x, encode_w, wchange);

    // 2) gi = seq @ w_ih^T + b_ih   (6400 x 432)
    {
        dim3 grid((G3 + 63) / 64, (Bn * Tn) / 64);
        gemm_tn<<<grid, 128, gemm_smem>>>(p_seq, w_ih, b_ih, p_gi, G3);
    }

    // 3) GRU recurrence (one CTA per batch row), writes h_last to out tail
    gru_kernel<<<Bn, G3, gru_smem>>>(w_hh, b_hh, hidden, out);

    // 4) dynamic_user = hseq @ fc_w^T + fc_b  (6400 x 128) -> out head
    {
        dim3 grid(En / 64, (Bn * Tn) / 64);
        gemm_tn<<<grid, 128, gemm_smem>>>(p_hseq, fc_w, fc_b, out, En);
    }
}

// round 8
// speedup vs baseline: 1.3691x; 1.1611x over previous
#include <cuda_runtime.h>
#include <cstdint>

#define Bn   128
#define Tn   50
#define MI   32
#define En   128
#define Dn   144
#define G3   432
#define KD   144
#define KH   72           // GEMM k-slab
#define KP2  76           // padded slab stride (floats)
#define CREG 96           // k-columns of w_hh in registers (48 ull pairs)
#define KSP  24           // remaining k-pairs of w_hh in smem (48 k-cols)

typedef unsigned long long ull;

__device__ float g_seq [Bn*Tn*Dn];
__device__ float g_gi  [Bn*Tn*G3];
__device__ float g_hseq[Bn*Tn*Dn];

// ---- f32x2 helpers ---------------------------------------------------------
__device__ __forceinline__ void fma2(ull& d, ull a, ull b) {
    asm("fma.rn.f32x2 %0, %1, %2, %0;" : "+l"(d) : "l"(a), "l"(b));
}
__device__ __forceinline__ float hsum2(ull v) {
    float lo, hi;
    asm("mov.b64 {%0,%1}, %2;" : "=f"(lo), "=f"(hi) : "l"(v));
    return lo + hi;
}
__device__ __forceinline__ ull pack2(float lo, float hi) {
    ull v;
    asm("mov.b64 %0, {%1,%2};" : "=l"(v) : "f"(lo), "f"(hi));
    return v;
}

// ---------------------------------------------------------------------------
// 0) no-op spacer (shifts ncu capture slot)
// ---------------------------------------------------------------------------
__global__ void noop_kernel() {}

// ---------------------------------------------------------------------------
// 1) basket embedding (1 warp does the 128-wide mean pool, float4 gathers)
// ---------------------------------------------------------------------------
__global__ void __launch_bounds__(64)
embed_kernel(const int* __restrict__ x,
             const float* __restrict__ encode_w,
             const float* __restrict__ wchange_w) {
    int bt = blockIdx.x;
    const int* xr = x + (size_t)bt * (MI + 1);
    __shared__ int s_items[MI];
    __shared__ int s_flag;
    int tid = threadIdx.x;
    if (tid < MI) s_items[tid] = xr[tid];
    if (tid == MI) s_flag = xr[MI];
    __syncthreads();

    if (tid < 32) {
        float4 acc = make_float4(0.f, 0.f, 0.f, 0.f);
        int cnt = 0;
        #pragma unroll
        for (int i = 0; i < MI; i++) {
            int it = s_items[i];                // warp-uniform
            if (it != 0) {
                cnt++;
                float4 v = *(const float4*)(encode_w + (size_t)it * En + 4 * tid);
                acc.x += v.x; acc.y += v.y; acc.z += v.z; acc.w += v.w;
            }
        }
        float inv = 1.f / (float)(cnt > 0 ? cnt : 1);
        acc.x *= inv; acc.y *= inv; acc.z *= inv; acc.w *= inv;
        *(float4*)(g_seq + (size_t)bt * Dn + 4 * tid) = acc;
    } else if (tid < 48) {
        g_seq[(size_t)bt * Dn + En + (tid - 32)] = wchange_w[s_flag * 16 + (tid - 32)];
    }
}

// ---------------------------------------------------------------------------
// 2) C[M,N] = A[M,144]*Bm[N,144]^T + bias
//    64x64 tile, 128 threads, 8x4 micro-tile, two 72-k slabs (38.9KB smem)
// ---------------------------------------------------------------------------
__global__ void __launch_bounds__(128)
gemm_tn(const float* __restrict__ A, const float* __restrict__ Bm,
        const float* __restrict__ bias, float* __restrict__ C, int N) {
    extern __shared__ float sm[];
    float* Ast = sm;              // [64][KP2]
    float* Bst = sm + 64 * KP2;   // [64][KP2]

    int tid = threadIdx.x;
    int m0 = blockIdx.y * 64, n0 = blockIdx.x * 64;
    int tx = tid & 15, ty = tid >> 4;           // n-lane(16), m-group(8)

    ull acc[8][4];
    #pragma unroll
    for (int i = 0; i < 8; i++)
        #pragma unroll
        for (int j = 0; j < 4; j++) acc[i][j] = 0ull;

    for (int ks = 0; ks < 2; ks++) {
        int k0 = ks * KH;
        #pragma unroll
        for (int p = 0; p < 9; p++) {
            int idx = tid + p * 128;
            int r = idx / 18, c = idx - 18 * r;
            *(float4*)(Ast + r * KP2 + 4 * c) =
                *(const float4*)(A + (size_t)(m0 + r) * KD + k0 + 4 * c);
        }
        #pragma unroll
        for (int p = 0; p < 9; p++) {
            int idx = tid + p * 128;
            int r = idx / 18, c = idx - 18 * r;
            float4 v = make_float4(0.f, 0.f, 0.f, 0.f);
            if (n0 + r < N)
                v = *(const float4*)(Bm + (size_t)(n0 + r) * KD + k0 + 4 * c);
            *(float4*)(Bst + r * KP2 + 4 * c) = v;
        }
        __syncthreads();

        const float* aBase = Ast + (8 * ty) * KP2;
        const ulonglong2* bP[4];
        #pragma unroll
        for (int j = 0; j < 4; j++)
            bP[j] = (const ulonglong2*)(Bst + (tx + 16 * j) * KP2);

        #pragma unroll 6
        for (int kq = 0; kq < 18; kq++) {
            ulonglong2 b[4];
            #pragma unroll
            for (int j = 0; j < 4; j++) b[j] = bP[j][kq];
            #pragma unroll
            for (int i = 0; i < 8; i++) {
                ulonglong2 a = ((const ulonglong2*)(aBase + i * KP2))[kq];
                #pragma unroll
                for (int j = 0; j < 4; j++) {
                    fma2(acc[i][j], a.x, b[j].x);
                    fma2(acc[i][j], a.y, b[j].y);
                }
            }
        }
        __syncthreads();
    }

    #pragma unroll
    for (int j = 0; j < 4; j++) {
        int n = n0 + tx + 16 * j;
        if (n < N) {
            float bv = bias[n];
            #pragma unroll
            for (int i = 0; i < 8; i++) {
                int m = m0 + 8 * ty + i;
                C[(size_t)m * N + n] = hsum2(acc[i][j]) + bv;
            }
        }
    }
}

// ---------------------------------------------------------------------------
// 3) GRU recurrence: one CTA per batch element, 432 threads = one gate row.
//    k<96 weights in regs (48 pairs), k>=96 in smem (24 pairs).
//    h-loads software-pipelined (3-deep rotating ulonglong2 buffer).
// ---------------------------------------------------------------------------
__global__ void __launch_bounds__(G3, 1)
gru_kernel(const float* __restrict__ w_hh, const float* __restrict__ b_hh,
           const float* __restrict__ hidden, float* __restrict__ out) {
    extern __shared__ float sm[];
    ull*   s_wtp = (ull*)sm;                 // [KSP][432]
    float* s_h   = sm + KSP * G3 * 2;        // [144]
    float* s_A   = s_h + Dn;                 // [432]
    float* s_gin = s_A + G3;                 // [144]

    int b = blockIdx.x;
    int j = threadIdx.x;

    const ull* wrow = (const ull*)(w_hh + (size_t)j * KD);   // 72 pairs
    ull w2[CREG / 2];
    #pragma unroll
    for (int p = 0; p < CREG / 2; p++) w2[p] = wrow[p];
    #pragma unroll
    for (int p = 0; p < KSP; p++) s_wtp[p * G3 + j] = wrow[CREG / 2 + p];

    if (j < Dn) s_h[j] = hidden[(size_t)b * Dn + j];
    float bias = b_hh[j];
    __syncthreads();

    const float* giB = g_gi + (size_t)b * Tn * G3;
    float* hsB       = g_hseq + (size_t)b * Tn * Dn;
    const ulonglong2* h2 = (const ulonglong2*)s_h;    // 36 quads (4 floats each)

    float gi_cur = giB[j];                    // prefetch t=0

    for (int t = 0; t < Tn; t++) {
        ull acc0 = pack2(bias, 0.f);
        ull acc1 = 0ull;

        // 3-deep pipelined dot product over 36 h-quads (12 groups of 3)
        ulonglong2 hq0 = h2[0], hq1 = h2[1], hq2 = h2[2];
        #pragma unroll
        for (int g = 0; g < 12; g++) {
            ulonglong2 c0 = hq0, c1 = hq1, c2 = hq2;
            if (g < 11) {                          // prefetch next group
                hq0 = h2[3 * g + 3];
                hq1 = h2[3 * g + 4];
                hq2 = h2[3 * g + 5];
            }
            #pragma unroll
            for (int e = 0; e < 3; e++) {
                int q = 3 * g + e;                 // quad index (compile-time)
                ulonglong2 c = (e == 0) ? c0 : (e == 1) ? c1 : c2;
                if (q < CREG / 4) {                // register weights
                    fma2(acc0, w2[2 * q], c.x);
                    fma2(acc1, w2[2 * q + 1], c.y);
                } else {                           // smem weight tail
                    int p = q - CREG / 4;
                    fma2(acc0, s_wtp[(2 * p) * G3 + j], c.x);
                    fma2(acc1, s_wtp[(2 * p + 1) * G3 + j], c.y);
                }
            }
        }
        float accf = hsum2(acc0) + hsum2(acc1);
        float gi_j = gi_cur;
        if (t + 1 < Tn) gi_cur = giB[(t + 1) * G3 + j];

        if (j < 2 * Dn) {
            s_A[j] = gi_j + accf;                  // r, z pre-activations
        } else {
            s_A[j] = accf;                         // h_n partial
            s_gin[j - 2 * Dn] = gi_j;              // i_n
        }
        __syncthreads();

        if (j < Dn) {
            float r = 1.f / (1.f + __expf(-s_A[j]));
            float z = 1.f / (1.f + __expf(-s_A[j + Dn]));
            float e = __expf(-2.f * (s_gin[j] + r * s_A[j + 2 * Dn]));
            float n = 2.f / (1.f + e) - 1.f;       // tanh
            float hn = (1.f - z) * n + z * s_h[j];
            s_h[j] = hn;
            hsB[t * Dn + j] = hn;
        }
        __syncthreads();
    }

    if (j < Dn) out[(size_t)Bn * Tn * En + (size_t)b * Dn + j] = s_h[j];
}

// ---------------------------------------------------------------------------
extern "C" void kernel_launch(void* const* d_in, const int* in_sizes, int n_in,
                              void* d_out, int out_size) {
    const int*   x        = (const int*)  d_in[0];
    const float* hidden   = (const float*)d_in[2];
    const float* encode_w = (const float*)d_in[3];
    const float* wchange  = (const float*)d_in[4];
    const float* w_ih     = (const float*)d_in[5];
    const float* w_hh     = (const float*)d_in[6];
    const float* b_ih     = (const float*)d_in[7];
    const float* b_hh     = (const float*)d_in[8];
    const float* fc_w     = (const float*)d_in[9];
    const float* fc_b     = (const float*)d_in[10];
    float* out = (float*)d_out;

    float *p_seq, *p_gi, *p_hseq;
    cudaGetSymbolAddress((void**)&p_seq,  g_seq);
    cudaGetSymbolAddress((void**)&p_gi,   g_gi);
    cudaGetSymbolAddress((void**)&p_hseq, g_hseq);

    const int gemm_smem = 2 * 64 * KP2 * 4;                       // 38912 B
    const int gru_smem  = (KSP * G3 * 2 + Dn + G3 + Dn) * 4;      // 85824 B
    cudaFuncSetAttribute(gru_kernel, cudaFuncAttributeMaxDynamicSharedMemorySize, gru_smem);

    // 1) embed
    embed_kernel<<<Bn * Tn, 64>>>(x, encode_w, wchange);

    // 2) gi = seq @ w_ih^T + b_ih   (6400 x 432)
    {
        dim3 grid((G3 + 63) / 64, (Bn * Tn) / 64);
        gemm_tn<<<grid, 128, gemm_smem>>>(p_seq, w_ih, b_ih, p_gi, G3);
    }

    // spacer so the ncu capture slot lands on the GRU kernel
    noop_kernel<<<1, 32>>>();

    // 3) GRU recurrence (one CTA per batch row), writes h_last to out tail
    gru_kernel<<<Bn, G3, gru_smem>>>(w_hh, b_hh, hidden, out);

    // 4) dynamic_user = hseq @ fc_w^T + fc_b  (6400 x 128) -> out head
    {
        dim3 grid(En / 64, (Bn * Tn) / 64);
        gemm_tn<<<grid, 128, gemm_smem>>>(p_hseq, fc_w, fc_b, out, En);
    }
}